// round 11
// baseline (speedup 1.0000x reference)
#include <cuda_runtime.h>
#include <cstdint>
#include <math.h>

#define T_TOK 2048
#define HD    2048
#define ID    768
#define NE    32
#define TOPK  4
#define NPAIR (T_TOK*TOPK)
#define MAXT  96
#define NPAD  (MAXT*128)

// ---------------- scratch ----------------
__device__ int   g_cnt[NE];
__device__ int   g_cur[NE];
__device__ int   g_tk_id[NPAIR];
__device__ float g_tk_w[NPAIR];
__device__ int   g_slot[NPAIR];
__device__ int   g_pair_tok[NPAD];
__device__ float g_pair_w[NPAD];
__device__ int   g_tile_e[MAXT];
__device__ int   g_tile_base[MAXT];
__device__ int   g_ntile;
__device__ float g_xtf[(size_t)T_TOK * HD];          // X pre-rounded to tf32
__device__ float g_act[(size_t)NPAD * ID];           // stage-A out, tf32-rounded
__device__ float g_pairout[(size_t)NPAD * HD];

// ---------------- helpers ----------------
__device__ __forceinline__ uint32_t smem_u32(const void* p) {
    uint32_t a;
    asm("{ .reg .u64 t; cvta.to.shared.u64 t, %1; cvt.u32.u64 %0, t; }" : "=r"(a) : "l"(p));
    return a;
}
__device__ __forceinline__ uint32_t tf32r(float f) {
    uint32_t u; asm("cvt.rna.tf32.f32 %0, %1;" : "=r"(u) : "f"(f)); return u;
}
__device__ __forceinline__ void cpasync16(uint32_t dst, const void* src) {
    asm volatile("cp.async.cg.shared.global [%0], [%1], 16;" :: "r"(dst), "l"(src));
}
#define CP_COMMIT() asm volatile("cp.async.commit_group;" ::: "memory")
#define CP_WAIT1()  asm volatile("cp.async.wait_group 1;" ::: "memory")
#define CP_WAIT0()  asm volatile("cp.async.wait_group 0;" ::: "memory")

__device__ __forceinline__ void mma8(float* c, const uint32_t* a, const uint32_t* b) {
    asm volatile("mma.sync.aligned.m16n8k8.row.col.f32.tf32.tf32.f32 "
        "{%0,%1,%2,%3}, {%4,%5,%6,%7}, {%8,%9}, {%0,%1,%2,%3};"
        : "+f"(c[0]), "+f"(c[1]), "+f"(c[2]), "+f"(c[3])
        : "r"(a[0]), "r"(a[1]), "r"(a[2]), "r"(a[3]), "r"(b[0]), "r"(b[1]));
}
#define LDSM4(r0,r1,r2,r3,addr) \
    asm volatile("ldmatrix.sync.aligned.m8n8.x4.shared.b16 {%0,%1,%2,%3}, [%4];" \
        : "=r"(r0), "=r"(r1), "=r"(r2), "=r"(r3) : "r"(addr))

#define ASTR 36     // A smem row stride (floats): 144B = 9x16B -> LDSM conflict-free
#define BSTR 136    // B smem k-row stride (floats): scalar LDS conflict-free
// floats: sA0 0, sA1 4608, sB0 9216, sB1 13568, wts 17920, end 18048
#define OFF_SA1 4608
#define OFF_SB0 9216
#define OFF_SB1 13568
#define OFF_WTS 17920
#define SM_BYTES (18048 * 4)

// ---------------- small kernels ----------------
// launch #0: zero pair lists AND per-expert counters (merged so stageA is launch #5)
__global__ void zeropair_kernel() {
    int p = blockIdx.x * 256 + threadIdx.x;
    if (p < NPAD) { g_pair_tok[p] = 0; g_pair_w[p] = 0.f; }
    if (blockIdx.x == 0 && threadIdx.x < NE) g_cnt[threadIdx.x] = 0;
}

__global__ void cvtx_kernel(const float* __restrict__ x) {
    int i = blockIdx.x * 256 + threadIdx.x;
    float4 v = ((const float4*)x)[i];
    float4 o = make_float4(__uint_as_float(tf32r(v.x)), __uint_as_float(tf32r(v.y)),
                           __uint_as_float(tf32r(v.z)), __uint_as_float(tf32r(v.w)));
    ((float4*)g_xtf)[i] = o;
}

__global__ void router_kernel(const float* __restrict__ x, const float* __restrict__ gw) {
    __shared__ float xs[HD];
    __shared__ float lg[NE];
    int t = blockIdx.x;
    const float4* xv  = (const float4*)(x + (size_t)t * HD);
    float4*       xsv = (float4*)xs;
    for (int i = threadIdx.x; i < HD/4; i += blockDim.x) xsv[i] = xv[i];
    __syncthreads();
    int warp = threadIdx.x >> 5, lane = threadIdx.x & 31;
    for (int e = warp; e < NE; e += 8) {
        const float4* w = (const float4*)(gw + (size_t)e * HD);
        float s = 0.f;
        #pragma unroll 4
        for (int h = lane; h < HD/4; h += 32) {
            float4 wv = w[h]; float4 xr = xsv[h];
            s += wv.x*xr.x + wv.y*xr.y + wv.z*xr.z + wv.w*xr.w;
        }
        #pragma unroll
        for (int o = 16; o; o >>= 1) s += __shfl_xor_sync(0xffffffffu, s, o);
        if (lane == 0) lg[e] = s;
    }
    __syncthreads();
    if (threadIdx.x == 0) {
        int sel[TOPK]; float sv[TOPK];
        unsigned used = 0u;
        #pragma unroll
        for (int k = 0; k < TOPK; k++) {
            float best = -1e30f; int bi = 0;
            for (int e2 = 0; e2 < NE; e2++)
                if (!((used >> e2) & 1u) && lg[e2] > best) { best = lg[e2]; bi = e2; }
            used |= 1u << bi; sel[k] = bi; sv[k] = best;
        }
        float mx = sv[0], den = 0.f, ww[TOPK];
        #pragma unroll
        for (int k = 0; k < TOPK; k++) { ww[k] = expf(sv[k] - mx); den += ww[k]; }
        #pragma unroll
        for (int k = 0; k < TOPK; k++) {
            g_tk_id[t*TOPK + k] = sel[k];
            g_tk_w [t*TOPK + k] = ww[k] / den;
            atomicAdd(&g_cnt[sel[k]], 1);
        }
    }
}

// warp-parallel scan+pad (was 9us single-thread)
__global__ void scanpad_kernel() {
    int lane = threadIdx.x & 31;
    int c = (lane < NE) ? g_cnt[lane] : 0;
    int tiles = (c + 127) >> 7;
    int pad = tiles * 128;
    // exclusive prefix of pad and tiles
    int poff = pad, toff = tiles;
    #pragma unroll
    for (int o = 1; o < 32; o <<= 1) {
        int pv = __shfl_up_sync(0xffffffffu, poff, o);
        int tv = __shfl_up_sync(0xffffffffu, toff, o);
        if (lane >= o) { poff += pv; toff += tv; }
    }
    int pbase = poff - pad, tbase = toff - tiles;
    if (lane < NE) {
        g_cur[lane] = pbase;
        for (int i = 0; i < tiles; i++) {
            g_tile_e[tbase + i] = lane;
            g_tile_base[tbase + i] = pbase + i*128;
        }
    }
    if (lane == 31) g_ntile = toff;
}

__global__ void fill_kernel() {
    int p = blockIdx.x * 256 + threadIdx.x;
    if (p >= NPAIR) return;
    int e = g_tk_id[p];
    int pos = atomicAdd(&g_cur[e], 1);
    g_pair_tok[pos] = p >> 2;
    g_pair_w [pos] = g_tk_w[p];
    g_slot[p] = pos;
}

__global__ void combine_kernel(float* __restrict__ out) {
    int t = blockIdx.x;
    int s0 = g_slot[t*4+0], s1 = g_slot[t*4+1], s2 = g_slot[t*4+2], s3 = g_slot[t*4+3];
    const float4* p0 = (const float4*)(g_pairout + (size_t)s0 * HD);
    const float4* p1 = (const float4*)(g_pairout + (size_t)s1 * HD);
    const float4* p2 = (const float4*)(g_pairout + (size_t)s2 * HD);
    const float4* p3 = (const float4*)(g_pairout + (size_t)s3 * HD);
    float4* o = (float4*)(out + (size_t)t * HD);
    for (int i = threadIdx.x; i < HD/4; i += 256) {
        float4 a = p0[i], b = p1[i], c = p2[i], d = p3[i];
        o[i] = make_float4(a.x+b.x+c.x+d.x, a.y+b.y+c.y+d.y,
                           a.z+b.z+c.z+d.z, a.w+b.w+c.w+d.w);
    }
}

// ---------------- stage A: warp tile m64 x n16-logical, ldmatrix A frags ----------------
__global__ void __launch_bounds__(256, 2)
stageA_kernel(const float* __restrict__ Wg, const float* __restrict__ Wu) {
    int mt = blockIdx.y;
    if (mt >= g_ntile) return;
    int e = g_tile_e[mt], base = g_tile_base[mt];
    int nb = blockIdx.x;  // 64 logical I cols

    extern __shared__ float sm[];
    float* sB[2] = { sm + OFF_SB0, sm + OFF_SB1 };
    float* wts = sm + OFF_WTS;
    uint32_t sAu[2] = { smem_u32(sm), smem_u32(sm + OFF_SA1) };
    uint32_t sBu[2] = { smem_u32(sB[0]), smem_u32(sB[1]) };

    int t = threadIdx.x;
    if (t < 128) wts[t] = g_pair_w[base + t];

    // A producer: thread -> (row, 64B half)
    int arow = t >> 1, aseg = t & 1;
    const float* asrc0 = g_xtf + (size_t)g_pair_tok[base + arow] * HD + aseg * 16;
    uint32_t adst = (uint32_t)(arow * (ASTR*4) + aseg * 64);
    // B producer: thread -> (k0, 16B col chunk)
    int bc = t & 31, bk0 = t >> 5;
    const float* Wge = Wg + (size_t)e * HD * ID + (size_t)nb * 64;
    const float* Wue = Wu + (size_t)e * HD * ID + (size_t)nb * 64;
    const float* bsrc0 = ((bc < 16) ? (Wge + bc*4) : (Wue + (bc-16)*4)) + (size_t)bk0 * ID;
    uint32_t bdst = (uint32_t)(bk0 * (BSTR*4) + bc * 16);

    int lane = t & 31, wid = t >> 5;
    int wm  = (wid & 1) * 64;        // 2 m-warp groups
    int wng = (wid >> 1) * 16;       // 4 logical-n warp groups
    int grp = lane >> 2, tg = lane & 3;
    uint32_t aoff = (uint32_t)((wm + (lane & 15)) * (ASTR*4) + (lane >> 4) * 16);

    float acc[4][4][4];   // [mfrag][0,1=g 2,3=u][frag]
    #pragma unroll
    for (int m = 0; m < 4; m++)
        #pragma unroll
        for (int n = 0; n < 4; n++)
            #pragma unroll
            for (int i = 0; i < 4; i++) acc[m][n][i] = 0.f;

    #pragma unroll
    for (int i = 0; i < 4; i++) cpasync16(sAu[0] + adst + i*16, asrc0 + i*4);
    #pragma unroll
    for (int i = 0; i < 4; i++) cpasync16(sBu[0] + bdst + i*8*(BSTR*4), bsrc0 + (size_t)i*8*ID);
    CP_COMMIT();

    for (int kc = 0; kc < 64; kc++) {
        int b = kc & 1;
        __syncthreads();
        if (kc + 1 < 64) {
            const float* as = asrc0 + (size_t)(kc+1) * 32;
            const float* bs = bsrc0 + (size_t)(kc+1) * 32 * ID;
            #pragma unroll
            for (int i = 0; i < 4; i++) cpasync16(sAu[b^1] + adst + i*16, as + i*4);
            #pragma unroll
            for (int i = 0; i < 4; i++) cpasync16(sBu[b^1] + bdst + i*8*(BSTR*4), bs + (size_t)i*8*ID);
            CP_COMMIT();
            CP_WAIT1();
        } else {
            CP_WAIT0();
        }
        __syncthreads();

        uint32_t abase = sAu[b] + aoff;
        const float* B = sB[b];
        #pragma unroll
        for (int ks = 0; ks < 4; ks++) {
            uint32_t af[4][4];
            #pragma unroll
            for (int m = 0; m < 4; m++)
                LDSM4(af[m][0], af[m][1], af[m][2], af[m][3], abase + m*(16*ASTR*4) + ks*32);
            int k = ks*8 + tg;
            #pragma unroll
            for (int n = 0; n < 2; n++) {
                int colg = wng + n*8 + grp;
                uint32_t bf[2];
                bf[0] = tf32r(B[k*BSTR + colg]);
                bf[1] = tf32r(B[(k+4)*BSTR + colg]);
                #pragma unroll
                for (int m = 0; m < 4; m++) mma8(acc[m][n], af[m], bf);
                bf[0] = tf32r(B[k*BSTR + 64 + colg]);
                bf[1] = tf32r(B[(k+4)*BSTR + 64 + colg]);
                #pragma unroll
                for (int m = 0; m < 4; m++) mma8(acc[m][n+2], af[m], bf);
            }
        }
    }

    // epilogue: silu(g)*u*wt, round to tf32, float2 stores
    #pragma unroll
    for (int m = 0; m < 4; m++) {
        int r0 = wm + m*16 + grp, r1 = r0 + 8;
        float w0 = wts[r0], w1 = wts[r1];
        #pragma unroll
        for (int n = 0; n < 2; n++) {
            int icol = nb*64 + wng + n*8 + 2*tg;
            float g0 = acc[m][n][0], g1 = acc[m][n][1];
            float g2 = acc[m][n][2], g3 = acc[m][n][3];
            float u0 = acc[m][n+2][0], u1 = acc[m][n+2][1];
            float u2 = acc[m][n+2][2], u3 = acc[m][n+2][3];
            float v0 = g0 / (1.f + __expf(-g0)) * u0 * w0;
            float v1 = g1 / (1.f + __expf(-g1)) * u1 * w0;
            float v2 = g2 / (1.f + __expf(-g2)) * u2 * w1;
            float v3 = g3 / (1.f + __expf(-g3)) * u3 * w1;
            *(float2*)(g_act + (size_t)(base + r0) * ID + icol) =
                make_float2(__uint_as_float(tf32r(v0)), __uint_as_float(tf32r(v1)));
            *(float2*)(g_act + (size_t)(base + r1) * ID + icol) =
                make_float2(__uint_as_float(tf32r(v2)), __uint_as_float(tf32r(v3)));
        }
    }
}

// ---------------- stage B: warp tile m64 x n32, ldmatrix A frags ----------------
__global__ void __launch_bounds__(256, 2)
stageB_kernel(const float* __restrict__ Wd) {
    int mt = blockIdx.y;
    if (mt >= g_ntile) return;
    int e = g_tile_e[mt], base = g_tile_base[mt];
    int nb = blockIdx.x;  // 128 HD cols

    extern __shared__ float sm[];
    float* sB[2] = { sm + OFF_SB0, sm + OFF_SB1 };
    uint32_t sAu[2] = { smem_u32(sm), smem_u32(sm + OFF_SA1) };
    uint32_t sBu[2] = { smem_u32(sB[0]), smem_u32(sB[1]) };

    int t = threadIdx.x;
    int arow = t >> 1, aseg = t & 1;
    const float* asrc0 = g_act + (size_t)(base + arow) * ID + aseg * 16;
    uint32_t adst = (uint32_t)(arow * (ASTR*4) + aseg * 64);
    int bc = t & 31, bk0 = t >> 5;
    const float* We = Wd + (size_t)e * ID * HD + (size_t)nb * 128;
    const float* bsrc0 = We + bc*4 + (size_t)bk0 * HD;
    uint32_t bdst = (uint32_t)(bk0 * (BSTR*4) + bc * 16);

    int lane = t & 31, wid = t >> 5;
    int wm = (wid & 1) * 64;
    int wn = (wid >> 1) * 32;
    int grp = lane >> 2, tg = lane & 3;
    uint32_t aoff = (uint32_t)((wm + (lane & 15)) * (ASTR*4) + (lane >> 4) * 16);

    float acc[4][4][4];
    #pragma unroll
    for (int m = 0; m < 4; m++)
        #pragma unroll
        for (int n = 0; n < 4; n++)
            #pragma unroll
            for (int i = 0; i < 4; i++) acc[m][n][i] = 0.f;

    #pragma unroll
    for (int i = 0; i < 4; i++) cpasync16(sAu[0] + adst + i*16, asrc0 + i*4);
    #pragma unroll
    for (int i = 0; i < 4; i++) cpasync16(sBu[0] + bdst + i*8*(BSTR*4), bsrc0 + (size_t)i*8*HD);
    CP_COMMIT();

    for (int kc = 0; kc < 24; kc++) {
        int b = kc & 1;
        __syncthreads();
        if (kc + 1 < 24) {
            const float* as = asrc0 + (size_t)(kc+1) * 32;
            const float* bs = bsrc0 + (size_t)(kc+1) * 32 * HD;
            #pragma unroll
            for (int i = 0; i < 4; i++) cpasync16(sAu[b^1] + adst + i*16, as + i*4);
            #pragma unroll
            for (int i = 0; i < 4; i++) cpasync16(sBu[b^1] + bdst + i*8*(BSTR*4), bs + (size_t)i*8*HD);
            CP_COMMIT();
            CP_WAIT1();
        } else {
            CP_WAIT0();
        }
        __syncthreads();

        uint32_t abase = sAu[b] + aoff;
        const float* B = sB[b];
        #pragma unroll
        for (int ks = 0; ks < 4; ks++) {
            uint32_t af[4][4];
            #pragma unroll
            for (int m = 0; m < 4; m++)
                LDSM4(af[m][0], af[m][1], af[m][2], af[m][3], abase + m*(16*ASTR*4) + ks*32);
            int k = ks*8 + tg;
            #pragma unroll
            for (int n = 0; n < 4; n++) {
                int col = wn + n*8 + grp;
                uint32_t bf[2];
                bf[0] = tf32r(B[k*BSTR + col]);
                bf[1] = tf32r(B[(k+4)*BSTR + col]);
                #pragma unroll
                for (int m = 0; m < 4; m++) mma8(acc[m][n], af[m], bf);
            }
        }
    }

    #pragma unroll
    for (int m = 0; m < 4; m++) {
        int r0 = wm + m*16 + grp, r1 = r0 + 8;
        #pragma unroll
        for (int n = 0; n < 4; n++) {
            int col = nb*128 + wn + n*8 + 2*tg;
            *(float2*)(g_pairout + (size_t)(base + r0) * HD + col) =
                make_float2(acc[m][n][0], acc[m][n][1]);
            *(float2*)(g_pairout + (size_t)(base + r1) * HD + col) =
                make_float2(acc[m][n][2], acc[m][n][3]);
        }
    }
}

// ---------------- launch ----------------
extern "C" void kernel_launch(void* const* d_in, const int* in_sizes, int n_in,
                              void* d_out, int out_size) {
    const float* x  = (const float*)d_in[0];
    const float* gw = (const float*)d_in[1];
    const float* Wg = (const float*)d_in[2];
    const float* Wu = (const float*)d_in[3];
    const float* Wd = (const float*)d_in[4];
    float* out = (float*)d_out;

    cudaFuncSetAttribute(stageA_kernel, cudaFuncAttributeMaxDynamicSharedMemorySize, SM_BYTES);
    cudaFuncSetAttribute(stageB_kernel, cudaFuncAttributeMaxDynamicSharedMemorySize, SM_BYTES);

    // Launch order chosen so stageA_kernel is launch #5 (ncu -s 5 -c 1 profiles it).
    zeropair_kernel<<<NPAD/256, 256>>>();                 // 0 (also zeroes g_cnt)
    cvtx_kernel<<<(T_TOK*HD/4)/256, 256>>>(x);            // 1
    router_kernel<<<T_TOK, 256>>>(x, gw);                 // 2
    scanpad_kernel<<<1, 32>>>();                          // 3
    fill_kernel<<<NPAIR/256, 256>>>();                    // 4
    stageA_kernel<<<dim3(ID/64, MAXT), 256, SM_BYTES>>>(Wg, Wu);   // 5 <- profiled
    stageB_kernel<<<dim3(HD/128, MAXT), 256, SM_BYTES>>>(Wd);      // 6
    combine_kernel<<<T_TOK, 256>>>(out);                  // 7
}

// round 12
// speedup vs baseline: 1.4765x; 1.4765x over previous
#include <cuda_runtime.h>
#include <cstdint>
#include <math.h>

#define T_TOK 2048
#define HD    2048
#define ID    768
#define NE    32
#define TOPK  4
#define NPAIR (T_TOK*TOPK)
#define MAXT  96
#define NPAD  (MAXT*128)

// ---------------- scratch ----------------
__device__ int   g_cnt[NE];
__device__ int   g_cur[NE];
__device__ int   g_tk_id[NPAIR];
__device__ float g_tk_w[NPAIR];
__device__ int   g_slot[NPAIR];
__device__ int   g_pair_tok[NPAD];
__device__ float g_pair_w[NPAD];
__device__ int   g_tile_e[MAXT];
__device__ int   g_tile_base[MAXT];
__device__ int   g_ntile;
__device__ float g_xtf[(size_t)T_TOK * HD];          // X pre-rounded to tf32
__device__ float g_act[(size_t)NPAD * ID];           // stage-A out, tf32-rounded
__device__ float g_pairout[(size_t)NPAD * HD];

// ---------------- helpers ----------------
__device__ __forceinline__ uint32_t smem_u32(const void* p) {
    uint32_t a;
    asm("{ .reg .u64 t; cvta.to.shared.u64 t, %1; cvt.u32.u64 %0, t; }" : "=r"(a) : "l"(p));
    return a;
}
__device__ __forceinline__ uint32_t tf32r(float f) {
    uint32_t u; asm("cvt.rna.tf32.f32 %0, %1;" : "=r"(u) : "f"(f)); return u;
}
__device__ __forceinline__ void cpasync16(uint32_t dst, const void* src) {
    asm volatile("cp.async.cg.shared.global [%0], [%1], 16;" :: "r"(dst), "l"(src));
}
#define CP_COMMIT() asm volatile("cp.async.commit_group;" ::: "memory")
#define CP_WAIT1()  asm volatile("cp.async.wait_group 1;" ::: "memory")
#define CP_WAIT0()  asm volatile("cp.async.wait_group 0;" ::: "memory")

__device__ __forceinline__ void mma8(float* c, const uint32_t* a, const uint32_t* b) {
    asm volatile("mma.sync.aligned.m16n8k8.row.col.f32.tf32.tf32.f32 "
        "{%0,%1,%2,%3}, {%4,%5,%6,%7}, {%8,%9}, {%0,%1,%2,%3};"
        : "+f"(c[0]), "+f"(c[1]), "+f"(c[2]), "+f"(c[3])
        : "r"(a[0]), "r"(a[1]), "r"(a[2]), "r"(a[3]), "r"(b[0]), "r"(b[1]));
}
#define LDSM4(r0,r1,r2,r3,addr) \
    asm volatile("ldmatrix.sync.aligned.m8n8.x4.shared.b16 {%0,%1,%2,%3}, [%4];" \
        : "=r"(r0), "=r"(r1), "=r"(r2), "=r"(r3) : "r"(addr))

#define ASTR 36     // A smem row stride (floats): 144B = 9x16B -> LDSM conflict-free
#define BSTR 136    // B smem k-row stride (floats): scalar LDS conflict-free
// floats: sA0 0, sA1 4608, sB0 9216, sB1 13568, wts 17920, end 18048
#define OFF_SA1 4608
#define OFF_SB0 9216
#define OFF_SB1 13568
#define OFF_WTS 17920
#define SM_BYTES (18048 * 4)

// ---------------- small kernels ----------------
// zero pair lists AND per-expert counters (merged)
__global__ void zeropair_kernel() {
    int p = blockIdx.x * 256 + threadIdx.x;
    if (p < NPAD) { g_pair_tok[p] = 0; g_pair_w[p] = 0.f; }
    if (blockIdx.x == 0 && threadIdx.x < NE) g_cnt[threadIdx.x] = 0;
}

__global__ void cvtx_kernel(const float* __restrict__ x) {
    int i = blockIdx.x * 256 + threadIdx.x;
    float4 v = ((const float4*)x)[i];
    float4 o = make_float4(__uint_as_float(tf32r(v.x)), __uint_as_float(tf32r(v.y)),
                           __uint_as_float(tf32r(v.z)), __uint_as_float(tf32r(v.w)));
    ((float4*)g_xtf)[i] = o;
}

__global__ void router_kernel(const float* __restrict__ x, const float* __restrict__ gw) {
    __shared__ float xs[HD];
    __shared__ float lg[NE];
    int t = blockIdx.x;
    const float4* xv  = (const float4*)(x + (size_t)t * HD);
    float4*       xsv = (float4*)xs;
    for (int i = threadIdx.x; i < HD/4; i += blockDim.x) xsv[i] = xv[i];
    __syncthreads();
    int warp = threadIdx.x >> 5, lane = threadIdx.x & 31;
    for (int e = warp; e < NE; e += 8) {
        const float4* w = (const float4*)(gw + (size_t)e * HD);
        float s = 0.f;
        #pragma unroll 4
        for (int h = lane; h < HD/4; h += 32) {
            float4 wv = w[h]; float4 xr = xsv[h];
            s += wv.x*xr.x + wv.y*xr.y + wv.z*xr.z + wv.w*xr.w;
        }
        #pragma unroll
        for (int o = 16; o; o >>= 1) s += __shfl_xor_sync(0xffffffffu, s, o);
        if (lane == 0) lg[e] = s;
    }
    __syncthreads();
    if (threadIdx.x == 0) {
        int sel[TOPK]; float sv[TOPK];
        unsigned used = 0u;
        #pragma unroll
        for (int k = 0; k < TOPK; k++) {
            float best = -1e30f; int bi = 0;
            for (int e2 = 0; e2 < NE; e2++)
                if (!((used >> e2) & 1u) && lg[e2] > best) { best = lg[e2]; bi = e2; }
            used |= 1u << bi; sel[k] = bi; sv[k] = best;
        }
        float mx = sv[0], den = 0.f, ww[TOPK];
        #pragma unroll
        for (int k = 0; k < TOPK; k++) { ww[k] = expf(sv[k] - mx); den += ww[k]; }
        #pragma unroll
        for (int k = 0; k < TOPK; k++) {
            g_tk_id[t*TOPK + k] = sel[k];
            g_tk_w [t*TOPK + k] = ww[k] / den;
            atomicAdd(&g_cnt[sel[k]], 1);
        }
    }
}

// warp-parallel scan+pad
__global__ void scanpad_kernel() {
    int lane = threadIdx.x & 31;
    int c = (lane < NE) ? g_cnt[lane] : 0;
    int tiles = (c + 127) >> 7;
    int pad = tiles * 128;
    int poff = pad, toff = tiles;
    #pragma unroll
    for (int o = 1; o < 32; o <<= 1) {
        int pv = __shfl_up_sync(0xffffffffu, poff, o);
        int tv = __shfl_up_sync(0xffffffffu, toff, o);
        if (lane >= o) { poff += pv; toff += tv; }
    }
    int pbase = poff - pad, tbase = toff - tiles;
    if (lane < NE) {
        g_cur[lane] = pbase;
        for (int i = 0; i < tiles; i++) {
            g_tile_e[tbase + i] = lane;
            g_tile_base[tbase + i] = pbase + i*128;
        }
    }
    if (lane == 31) g_ntile = toff;
}

__global__ void fill_kernel() {
    int p = blockIdx.x * 256 + threadIdx.x;
    if (p >= NPAIR) return;
    int e = g_tk_id[p];
    int pos = atomicAdd(&g_cur[e], 1);
    g_pair_tok[pos] = p >> 2;
    g_pair_w [pos] = g_tk_w[p];
    g_slot[p] = pos;
}

__global__ void combine_kernel(float* __restrict__ out) {
    int t = blockIdx.x;
    int s0 = g_slot[t*4+0], s1 = g_slot[t*4+1], s2 = g_slot[t*4+2], s3 = g_slot[t*4+3];
    const float4* p0 = (const float4*)(g_pairout + (size_t)s0 * HD);
    const float4* p1 = (const float4*)(g_pairout + (size_t)s1 * HD);
    const float4* p2 = (const float4*)(g_pairout + (size_t)s2 * HD);
    const float4* p3 = (const float4*)(g_pairout + (size_t)s3 * HD);
    float4* o = (float4*)(out + (size_t)t * HD);
    for (int i = threadIdx.x; i < HD/4; i += 256) {
        float4 a = p0[i], b = p1[i], c = p2[i], d = p3[i];
        o[i] = make_float4(a.x+b.x+c.x+d.x, a.y+b.y+c.y+d.y,
                           a.z+b.z+c.z+d.z, a.w+b.w+c.w+d.w);
    }
}

// ---------------- stage A: warp tile m64 x n16-logical, ldmatrix A frags ----------------
__global__ void __launch_bounds__(256, 2)
stageA_kernel(const float* __restrict__ Wg, const float* __restrict__ Wu) {
    int mt = blockIdx.y;
    if (mt >= g_ntile) return;
    int e = g_tile_e[mt], base = g_tile_base[mt];
    int nb = blockIdx.x;  // 64 logical I cols

    extern __shared__ float sm[];
    float* sB[2] = { sm + OFF_SB0, sm + OFF_SB1 };
    float* wts = sm + OFF_WTS;
    uint32_t sAu[2] = { smem_u32(sm), smem_u32(sm + OFF_SA1) };
    uint32_t sBu[2] = { smem_u32(sB[0]), smem_u32(sB[1]) };

    int t = threadIdx.x;
    if (t < 128) wts[t] = g_pair_w[base + t];

    int arow = t >> 1, aseg = t & 1;
    const float* asrc0 = g_xtf + (size_t)g_pair_tok[base + arow] * HD + aseg * 16;
    uint32_t adst = (uint32_t)(arow * (ASTR*4) + aseg * 64);
    int bc = t & 31, bk0 = t >> 5;
    const float* Wge = Wg + (size_t)e * HD * ID + (size_t)nb * 64;
    const float* Wue = Wu + (size_t)e * HD * ID + (size_t)nb * 64;
    const float* bsrc0 = ((bc < 16) ? (Wge + bc*4) : (Wue + (bc-16)*4)) + (size_t)bk0 * ID;
    uint32_t bdst = (uint32_t)(bk0 * (BSTR*4) + bc * 16);

    int lane = t & 31, wid = t >> 5;
    int wm  = (wid & 1) * 64;
    int wng = (wid >> 1) * 16;
    int grp = lane >> 2, tg = lane & 3;
    uint32_t aoff = (uint32_t)((wm + (lane & 15)) * (ASTR*4) + (lane >> 4) * 16);

    float acc[4][4][4];   // [mfrag][0,1=g 2,3=u][frag]
    #pragma unroll
    for (int m = 0; m < 4; m++)
        #pragma unroll
        for (int n = 0; n < 4; n++)
            #pragma unroll
            for (int i = 0; i < 4; i++) acc[m][n][i] = 0.f;

    #pragma unroll
    for (int i = 0; i < 4; i++) cpasync16(sAu[0] + adst + i*16, asrc0 + i*4);
    #pragma unroll
    for (int i = 0; i < 4; i++) cpasync16(sBu[0] + bdst + i*8*(BSTR*4), bsrc0 + (size_t)i*8*ID);
    CP_COMMIT();

    for (int kc = 0; kc < 64; kc++) {
        int b = kc & 1;
        __syncthreads();
        if (kc + 1 < 64) {
            const float* as = asrc0 + (size_t)(kc+1) * 32;
            const float* bs = bsrc0 + (size_t)(kc+1) * 32 * ID;
            #pragma unroll
            for (int i = 0; i < 4; i++) cpasync16(sAu[b^1] + adst + i*16, as + i*4);
            #pragma unroll
            for (int i = 0; i < 4; i++) cpasync16(sBu[b^1] + bdst + i*8*(BSTR*4), bs + (size_t)i*8*ID);
            CP_COMMIT();
            CP_WAIT1();
        } else {
            CP_WAIT0();
        }
        __syncthreads();

        uint32_t abase = sAu[b] + aoff;
        const float* B = sB[b];
        #pragma unroll
        for (int ks = 0; ks < 4; ks++) {
            uint32_t af[4][4];
            #pragma unroll
            for (int m = 0; m < 4; m++)
                LDSM4(af[m][0], af[m][1], af[m][2], af[m][3], abase + m*(16*ASTR*4) + ks*32);
            int k = ks*8 + tg;
            #pragma unroll
            for (int n = 0; n < 2; n++) {
                int colg = wng + n*8 + grp;
                uint32_t bf[2];
                bf[0] = tf32r(B[k*BSTR + colg]);
                bf[1] = tf32r(B[(k+4)*BSTR + colg]);
                #pragma unroll
                for (int m = 0; m < 4; m++) mma8(acc[m][n], af[m], bf);
                bf[0] = tf32r(B[k*BSTR + 64 + colg]);
                bf[1] = tf32r(B[(k+4)*BSTR + 64 + colg]);
                #pragma unroll
                for (int m = 0; m < 4; m++) mma8(acc[m][n+2], af[m], bf);
            }
        }
    }

    #pragma unroll
    for (int m = 0; m < 4; m++) {
        int r0 = wm + m*16 + grp, r1 = r0 + 8;
        float w0 = wts[r0], w1 = wts[r1];
        #pragma unroll
        for (int n = 0; n < 2; n++) {
            int icol = nb*64 + wng + n*8 + 2*tg;
            float g0 = acc[m][n][0], g1 = acc[m][n][1];
            float g2 = acc[m][n][2], g3 = acc[m][n][3];
            float u0 = acc[m][n+2][0], u1 = acc[m][n+2][1];
            float u2 = acc[m][n+2][2], u3 = acc[m][n+2][3];
            float v0 = g0 / (1.f + __expf(-g0)) * u0 * w0;
            float v1 = g1 / (1.f + __expf(-g1)) * u1 * w0;
            float v2 = g2 / (1.f + __expf(-g2)) * u2 * w1;
            float v3 = g3 / (1.f + __expf(-g3)) * u3 * w1;
            *(float2*)(g_act + (size_t)(base + r0) * ID + icol) =
                make_float2(__uint_as_float(tf32r(v0)), __uint_as_float(tf32r(v1)));
            *(float2*)(g_act + (size_t)(base + r1) * ID + icol) =
                make_float2(__uint_as_float(tf32r(v2)), __uint_as_float(tf32r(v3)));
        }
    }
}

// ---------------- stage B: warp tile m64 x n32, ldmatrix A frags ----------------
__global__ void __launch_bounds__(256, 2)
stageB_kernel(const float* __restrict__ Wd) {
    int mt = blockIdx.y;
    if (mt >= g_ntile) return;
    int e = g_tile_e[mt], base = g_tile_base[mt];
    int nb = blockIdx.x;  // 128 HD cols

    extern __shared__ float sm[];
    float* sB[2] = { sm + OFF_SB0, sm + OFF_SB1 };
    uint32_t sAu[2] = { smem_u32(sm), smem_u32(sm + OFF_SA1) };
    uint32_t sBu[2] = { smem_u32(sB[0]), smem_u32(sB[1]) };

    int t = threadIdx.x;
    int arow = t >> 1, aseg = t & 1;
    const float* asrc0 = g_act + (size_t)(base + arow) * ID + aseg * 16;
    uint32_t adst = (uint32_t)(arow * (ASTR*4) + aseg * 64);
    int bc = t & 31, bk0 = t >> 5;
    const float* We = Wd + (size_t)e * ID * HD + (size_t)nb * 128;
    const float* bsrc0 = We + bc*4 + (size_t)bk0 * HD;
    uint32_t bdst = (uint32_t)(bk0 * (BSTR*4) + bc * 16);

    int lane = t & 31, wid = t >> 5;
    int wm = (wid & 1) * 64;
    int wn = (wid >> 1) * 32;
    int grp = lane >> 2, tg = lane & 3;
    uint32_t aoff = (uint32_t)((wm + (lane & 15)) * (ASTR*4) + (lane >> 4) * 16);

    float acc[4][4][4];
    #pragma unroll
    for (int m = 0; m < 4; m++)
        #pragma unroll
        for (int n = 0; n < 4; n++)
            #pragma unroll
            for (int i = 0; i < 4; i++) acc[m][n][i] = 0.f;

    #pragma unroll
    for (int i = 0; i < 4; i++) cpasync16(sAu[0] + adst + i*16, asrc0 + i*4);
    #pragma unroll
    for (int i = 0; i < 4; i++) cpasync16(sBu[0] + bdst + i*8*(BSTR*4), bsrc0 + (size_t)i*8*HD);
    CP_COMMIT();

    for (int kc = 0; kc < 24; kc++) {
        int b = kc & 1;
        __syncthreads();
        if (kc + 1 < 24) {
            const float* as = asrc0 + (size_t)(kc+1) * 32;
            const float* bs = bsrc0 + (size_t)(kc+1) * 32 * HD;
            #pragma unroll
            for (int i = 0; i < 4; i++) cpasync16(sAu[b^1] + adst + i*16, as + i*4);
            #pragma unroll
            for (int i = 0; i < 4; i++) cpasync16(sBu[b^1] + bdst + i*8*(BSTR*4), bs + (size_t)i*8*HD);
            CP_COMMIT();
            CP_WAIT1();
        } else {
            CP_WAIT0();
        }
        __syncthreads();

        uint32_t abase = sAu[b] + aoff;
        const float* B = sB[b];
        #pragma unroll
        for (int ks = 0; ks < 4; ks++) {
            uint32_t af[4][4];
            #pragma unroll
            for (int m = 0; m < 4; m++)
                LDSM4(af[m][0], af[m][1], af[m][2], af[m][3], abase + m*(16*ASTR*4) + ks*32);
            int k = ks*8 + tg;
            #pragma unroll
            for (int n = 0; n < 4; n++) {
                int col = wn + n*8 + grp;
                uint32_t bf[2];
                bf[0] = tf32r(B[k*BSTR + col]);
                bf[1] = tf32r(B[(k+4)*BSTR + col]);
                #pragma unroll
                for (int m = 0; m < 4; m++) mma8(acc[m][n], af[m], bf);
            }
        }
    }

    #pragma unroll
    for (int m = 0; m < 4; m++) {
        int r0 = wm + m*16 + grp, r1 = r0 + 8;
        #pragma unroll
        for (int n = 0; n < 4; n++) {
            int col = nb*128 + wn + n*8 + 2*tg;
            *(float2*)(g_pairout + (size_t)(base + r0) * HD + col) =
                make_float2(acc[m][n][0], acc[m][n][1]);
            *(float2*)(g_pairout + (size_t)(base + r1) * HD + col) =
                make_float2(acc[m][n][2], acc[m][n][3]);
        }
    }
}

// ---------------- launch (R7 order) ----------------
extern "C" void kernel_launch(void* const* d_in, const int* in_sizes, int n_in,
                              void* d_out, int out_size) {
    const float* x  = (const float*)d_in[0];
    const float* gw = (const float*)d_in[1];
    const float* Wg = (const float*)d_in[2];
    const float* Wu = (const float*)d_in[3];
    const float* Wd = (const float*)d_in[4];
    float* out = (float*)d_out;

    cudaFuncSetAttribute(stageA_kernel, cudaFuncAttributeMaxDynamicSharedMemorySize, SM_BYTES);
    cudaFuncSetAttribute(stageB_kernel, cudaFuncAttributeMaxDynamicSharedMemorySize, SM_BYTES);

    zeropair_kernel<<<NPAD/256, 256>>>();                 // also zeroes g_cnt
    cvtx_kernel<<<(T_TOK*HD/4)/256, 256>>>(x);
    router_kernel<<<T_TOK, 256>>>(x, gw);
    scanpad_kernel<<<1, 32>>>();
    fill_kernel<<<NPAIR/256, 256>>>();
    stageA_kernel<<<dim3(ID/64, MAXT), 256, SM_BYTES>>>(Wg, Wu);
    stageB_kernel<<<dim3(HD/128, MAXT), 256, SM_BYTES>>>(Wd);
    combine_kernel<<<T_TOK, 256>>>(out);
}